// round 7
// baseline (speedup 1.0000x reference)
#include <cuda_runtime.h>
#include <math.h>

// Problem constants
#define B_   8
#define C_   256
#define SQ_  4096   // 64*64 query pixels
#define SK_  1024   // 32*32 kv pixels
#define NH_  8
#define D_   32
#define NP_  4
#define OC_  64     // offset conv out channels = NH*NP*2
#define KC_  2304   // C_*9 im2col depth

// Packed fp32x2 FMA: d = a*b + d elementwise on (lo,hi). Bit-exact fp32.
#define FMA2(acc, a, b) \
    asm("fma.rn.f32x2 %0, %1, %2, %3;" : "=l"(acc) : "l"(a), "l"(b), "l"(acc))

// Scratch (device globals — no allocation allowed)
__device__ float g_q  [B_ * SQ_ * C_];   // (b, s, c)  channel-last
__device__ float g_k  [B_ * SK_ * C_];   // (b, sk, c)
__device__ float g_v  [B_ * SK_ * C_];   // (b, sk, c)
__device__ float g_off[B_ * SQ_ * OC_];  // (b, s, oc) -> final sample coords (kv pixel space)
__device__ float g_att[B_ * SQ_ * C_];   // (b, s, c)

// ---------------------------------------------------------------------------
// Q projection: g_q[b][s][o] = sum_c q_w[o][c] * X[b][c][s]
// 64x64 tile, 16x16 threads, 4x4 microtile.
// X tile stored DUPLICATED (x,x per element) so LDS.128 yields (xi,xi) pairs;
// weight tile k-major so LDS.128 yields (w0,w1),(w2,w3) pairs.
// Mainloop: 3x LDS.128 + 8x FFMA2 per k-step (16 FMAs).
// ---------------------------------------------------------------------------
__global__ __launch_bounds__(256)
void gemm_q_kernel(const float* __restrict__ X, const float* __restrict__ W) {
    int b  = blockIdx.z;
    int o0 = blockIdx.y * 64;
    int s0 = blockIdx.x * 64;
    int tx = threadIdx.x;          // 0..15 -> s
    int ty = threadIdx.y;          // 0..15 -> o
    int tid = ty * 16 + tx;

    __shared__ __align__(16) float Xs2[16][128];  // [k][2*s] duplicated
    __shared__ __align__(16) float Wt[16][68];    // [k][o] k-major

    unsigned long long acc01[4], acc23[4];
#pragma unroll
    for (int i = 0; i < 4; i++) { acc01[i] = 0ull; acc23[i] = 0ull; }

    for (int kc = 0; kc < C_; kc += 16) {
        {   // load X tile: 16k x 64s, duplicate into smem
            int kk = tid >> 4;
            int sc = (tid & 15) * 4;
            float4 xv = *reinterpret_cast<const float4*>(
                X + ((size_t)(b * C_ + kc + kk)) * SQ_ + s0 + sc);
            *reinterpret_cast<float4*>(&Xs2[kk][2 * sc]) =
                make_float4(xv.x, xv.x, xv.y, xv.y);
            *reinterpret_cast<float4*>(&Xs2[kk][2 * sc + 4]) =
                make_float4(xv.z, xv.z, xv.w, xv.w);
        }
        {   // load W tile (o-major in gmem) -> k-major smem
            int row = tid >> 2;            // o: 0..63
            int col = (tid & 3) * 4;       // k: 0,4,8,12
            float4 wv = *reinterpret_cast<const float4*>(
                W + (size_t)(o0 + row) * C_ + kc + col);
            Wt[col + 0][row] = wv.x;
            Wt[col + 1][row] = wv.y;
            Wt[col + 2][row] = wv.z;
            Wt[col + 3][row] = wv.w;
        }
        __syncthreads();
#pragma unroll
        for (int kk = 0; kk < 16; kk++) {
            ulonglong2 xa = *reinterpret_cast<const ulonglong2*>(&Xs2[kk][tx * 8]);
            ulonglong2 xb = *reinterpret_cast<const ulonglong2*>(&Xs2[kk][tx * 8 + 4]);
            ulonglong2 wp = *reinterpret_cast<const ulonglong2*>(&Wt[kk][ty * 4]);
            FMA2(acc01[0], xa.x, wp.x); FMA2(acc23[0], xa.x, wp.y);
            FMA2(acc01[1], xa.y, wp.x); FMA2(acc23[1], xa.y, wp.y);
            FMA2(acc01[2], xb.x, wp.x); FMA2(acc23[2], xb.x, wp.y);
            FMA2(acc01[3], xb.y, wp.x); FMA2(acc23[3], xb.y, wp.y);
        }
        __syncthreads();
    }
#pragma unroll
    for (int i = 0; i < 4; i++) {
        float2 f01 = *reinterpret_cast<float2*>(&acc01[i]);
        float2 f23 = *reinterpret_cast<float2*>(&acc23[i]);
        *reinterpret_cast<float4*>(
            g_q + ((size_t)b * SQ_ + s0 + tx * 4 + i) * C_ + o0 + ty * 4) =
            make_float4(f01.x, f01.y, f23.x, f23.y);
    }
}

// ---------------------------------------------------------------------------
// Fused K+V projection (FFMA2 mainloop, duplicated X tile).
// ---------------------------------------------------------------------------
__global__ __launch_bounds__(256)
void gemm_kv_kernel(const float* __restrict__ X,
                    const float* __restrict__ Wk_g,
                    const float* __restrict__ Wv_g) {
    int b  = blockIdx.z;
    int o0 = blockIdx.y * 64;
    int s0 = blockIdx.x * 64;
    int tx = threadIdx.x;
    int ty = threadIdx.y;
    int tid = ty * 16 + tx;

    __shared__ __align__(16) float Xs2[16][128];
    __shared__ __align__(16) float Wkt[16][68];
    __shared__ __align__(16) float Wvt[16][68];

    unsigned long long ak01[4], ak23[4], av01[4], av23[4];
#pragma unroll
    for (int i = 0; i < 4; i++) {
        ak01[i] = 0ull; ak23[i] = 0ull; av01[i] = 0ull; av23[i] = 0ull;
    }

    for (int kc = 0; kc < C_; kc += 16) {
        {
            int kk = tid >> 4;
            int sc = (tid & 15) * 4;
            float4 xv = *reinterpret_cast<const float4*>(
                X + ((size_t)(b * C_ + kc + kk)) * SK_ + s0 + sc);
            *reinterpret_cast<float4*>(&Xs2[kk][2 * sc]) =
                make_float4(xv.x, xv.x, xv.y, xv.y);
            *reinterpret_cast<float4*>(&Xs2[kk][2 * sc + 4]) =
                make_float4(xv.z, xv.z, xv.w, xv.w);
        }
        {
            int row = tid >> 2;
            int col = (tid & 3) * 4;
            size_t woff = (size_t)(o0 + row) * C_ + kc + col;
            float4 wk = *reinterpret_cast<const float4*>(Wk_g + woff);
            float4 wv = *reinterpret_cast<const float4*>(Wv_g + woff);
            Wkt[col + 0][row] = wk.x; Wkt[col + 1][row] = wk.y;
            Wkt[col + 2][row] = wk.z; Wkt[col + 3][row] = wk.w;
            Wvt[col + 0][row] = wv.x; Wvt[col + 1][row] = wv.y;
            Wvt[col + 2][row] = wv.z; Wvt[col + 3][row] = wv.w;
        }
        __syncthreads();
#pragma unroll
        for (int kk = 0; kk < 16; kk++) {
            ulonglong2 xa = *reinterpret_cast<const ulonglong2*>(&Xs2[kk][tx * 8]);
            ulonglong2 xb = *reinterpret_cast<const ulonglong2*>(&Xs2[kk][tx * 8 + 4]);
            ulonglong2 kp = *reinterpret_cast<const ulonglong2*>(&Wkt[kk][ty * 4]);
            ulonglong2 vp = *reinterpret_cast<const ulonglong2*>(&Wvt[kk][ty * 4]);
            FMA2(ak01[0], xa.x, kp.x); FMA2(ak23[0], xa.x, kp.y);
            FMA2(ak01[1], xa.y, kp.x); FMA2(ak23[1], xa.y, kp.y);
            FMA2(ak01[2], xb.x, kp.x); FMA2(ak23[2], xb.x, kp.y);
            FMA2(ak01[3], xb.y, kp.x); FMA2(ak23[3], xb.y, kp.y);
            FMA2(av01[0], xa.x, vp.x); FMA2(av23[0], xa.x, vp.y);
            FMA2(av01[1], xa.y, vp.x); FMA2(av23[1], xa.y, vp.y);
            FMA2(av01[2], xb.x, vp.x); FMA2(av23[2], xb.x, vp.y);
            FMA2(av01[3], xb.y, vp.x); FMA2(av23[3], xb.y, vp.y);
        }
        __syncthreads();
    }
#pragma unroll
    for (int i = 0; i < 4; i++) {
        size_t base = ((size_t)b * SK_ + s0 + tx * 4 + i) * C_ + o0 + ty * 4;
        float2 k01 = *reinterpret_cast<float2*>(&ak01[i]);
        float2 k23 = *reinterpret_cast<float2*>(&ak23[i]);
        float2 v01 = *reinterpret_cast<float2*>(&av01[i]);
        float2 v23 = *reinterpret_cast<float2*>(&av23[i]);
        *reinterpret_cast<float4*>(g_k + base) = make_float4(k01.x, k01.y, k23.x, k23.y);
        *reinterpret_cast<float4*>(g_v + base) = make_float4(v01.x, v01.y, v23.x, v23.y);
    }
}

// ---------------------------------------------------------------------------
// GEMM B (final projection): out[b][o][s] = sum_c W[o][c] * g_att[b][s][c]
// A tile duplicated, W tile k-major, FFMA2 mainloop.
// ---------------------------------------------------------------------------
__global__ __launch_bounds__(256)
void gemm_out_kernel(const float* __restrict__ W, float* __restrict__ Y) {
    int b  = blockIdx.z;
    int o0 = blockIdx.y * 64;
    int s0 = blockIdx.x * 64;
    int tx = threadIdx.x;          // s
    int ty = threadIdx.y;          // o
    int tid = ty * 16 + tx;

    __shared__ __align__(16) float As2[16][128];  // [k][2*s] duplicated
    __shared__ __align__(16) float Wt[16][68];    // [k][o]

    unsigned long long acc01[4], acc23[4];
#pragma unroll
    for (int i = 0; i < 4; i++) { acc01[i] = 0ull; acc23[i] = 0ull; }

    for (int kc = 0; kc < C_; kc += 16) {
        int row = tid >> 2;
        int col = (tid & 3) * 4;
        {
            float4 av = *reinterpret_cast<const float4*>(
                g_att + ((size_t)b * SQ_ + s0 + row) * C_ + kc + col);
            *reinterpret_cast<float2*>(&As2[col + 0][2 * row]) = make_float2(av.x, av.x);
            *reinterpret_cast<float2*>(&As2[col + 1][2 * row]) = make_float2(av.y, av.y);
            *reinterpret_cast<float2*>(&As2[col + 2][2 * row]) = make_float2(av.z, av.z);
            *reinterpret_cast<float2*>(&As2[col + 3][2 * row]) = make_float2(av.w, av.w);
        }
        {
            float4 wv = *reinterpret_cast<const float4*>(
                W + (size_t)(o0 + row) * C_ + kc + col);
            Wt[col + 0][row] = wv.x; Wt[col + 1][row] = wv.y;
            Wt[col + 2][row] = wv.z; Wt[col + 3][row] = wv.w;
        }
        __syncthreads();
#pragma unroll
        for (int kk = 0; kk < 16; kk++) {
            ulonglong2 xa = *reinterpret_cast<const ulonglong2*>(&As2[kk][tx * 8]);
            ulonglong2 xb = *reinterpret_cast<const ulonglong2*>(&As2[kk][tx * 8 + 4]);
            ulonglong2 wp = *reinterpret_cast<const ulonglong2*>(&Wt[kk][ty * 4]);
            FMA2(acc01[0], xa.x, wp.x); FMA2(acc23[0], xa.x, wp.y);
            FMA2(acc01[1], xa.y, wp.x); FMA2(acc23[1], xa.y, wp.y);
            FMA2(acc01[2], xb.x, wp.x); FMA2(acc23[2], xb.x, wp.y);
            FMA2(acc01[3], xb.y, wp.x); FMA2(acc23[3], xb.y, wp.y);
        }
        __syncthreads();
    }
    // acc01[i] = (o_{ty*4}, o_{ty*4+1}) for s = s0+tx*4+i; output is (b, o, s):
    // transpose in registers and store float4 along s.
    float o_s[4][4];
#pragma unroll
    for (int i = 0; i < 4; i++) {
        float2 f01 = *reinterpret_cast<float2*>(&acc01[i]);
        float2 f23 = *reinterpret_cast<float2*>(&acc23[i]);
        o_s[i][0] = f01.x; o_s[i][1] = f01.y; o_s[i][2] = f23.x; o_s[i][3] = f23.y;
    }
#pragma unroll
    for (int j = 0; j < 4; j++) {
        *reinterpret_cast<float4*>(
            Y + ((size_t)b * C_ + o0 + ty * 4 + j) * SQ_ + s0 + tx * 4) =
            make_float4(o_s[0][j], o_s[1][j], o_s[2][j], o_s[3][j]);
    }
}

// ---------------------------------------------------------------------------
// 3x3 SAME conv as implicit GEMM + fused coordinate epilogue (FFMA2 mainloop).
// Epilogue converts each offset logit into the final kv-pixel-space coord:
//   f = ((base + tanh(val)*0.25) + 1) * 16 - 0.5
// ---------------------------------------------------------------------------
__global__ __launch_bounds__(256)
void conv_off_gemm_kernel(const float* __restrict__ X, const float* __restrict__ W,
                          const float* __restrict__ bias) {
    int b  = blockIdx.y;
    int y  = blockIdx.x;           // image row = s-tile of 64 pixels
    int tx = threadIdx.x;          // 0..15 -> s (x position groups)
    int ty = threadIdx.y;          // 0..15 -> oc
    int tid = ty * 16 + tx;

    __shared__ __align__(16) float Xs2[16][128];  // [k][2*x] duplicated
    __shared__ __align__(16) float Wt[16][68];    // [k][oc]

    unsigned long long acc01[4], acc23[4];
#pragma unroll
    for (int i = 0; i < 4; i++) { acc01[i] = 0ull; acc23[i] = 0ull; }

    for (int kc = 0; kc < KC_; kc += 16) {
        {   // gather im2col tile: 16 K-rows x 64 x-positions, duplicated
            int kk   = tid >> 4;            // 0..15
            int xc   = (tid & 15) * 4;      // 0,4,...,60
            int kidx = kc + kk;
            int c    = kidx / 9;
            int r9   = kidx - c * 9;
            int ky   = r9 / 3 - 1;          // -1,0,1
            int kx   = r9 - (r9 / 3) * 3 - 1;
            int gy   = y + ky;
            float v0 = 0.f, v1 = 0.f, v2 = 0.f, v3 = 0.f;
            if (gy >= 0 && gy < 64) {
                const float* rowp = X + (((size_t)b * C_ + c) * 64 + gy) * 64;
                int g0 = xc + 0 + kx, g1 = xc + 1 + kx, g2 = xc + 2 + kx, g3 = xc + 3 + kx;
                if (g0 >= 0 && g0 < 64) v0 = rowp[g0];
                if (g1 >= 0 && g1 < 64) v1 = rowp[g1];
                if (g2 >= 0 && g2 < 64) v2 = rowp[g2];
                if (g3 >= 0 && g3 < 64) v3 = rowp[g3];
            }
            *reinterpret_cast<float4*>(&Xs2[kk][2 * xc]) = make_float4(v0, v0, v1, v1);
            *reinterpret_cast<float4*>(&Xs2[kk][2 * xc + 4]) = make_float4(v2, v2, v3, v3);
        }
        {   // load W tile (oc-major in gmem, contiguous k) -> k-major smem
            int row = tid >> 2;            // oc
            int col = (tid & 3) * 4;       // k
            float4 wv = *reinterpret_cast<const float4*>(
                W + (size_t)row * KC_ + kc + col);
            Wt[col + 0][row] = wv.x;
            Wt[col + 1][row] = wv.y;
            Wt[col + 2][row] = wv.z;
            Wt[col + 3][row] = wv.w;
        }
        __syncthreads();
#pragma unroll
        for (int kk = 0; kk < 16; kk++) {
            ulonglong2 xa = *reinterpret_cast<const ulonglong2*>(&Xs2[kk][tx * 8]);
            ulonglong2 xb = *reinterpret_cast<const ulonglong2*>(&Xs2[kk][tx * 8 + 4]);
            ulonglong2 wp = *reinterpret_cast<const ulonglong2*>(&Wt[kk][ty * 4]);
            FMA2(acc01[0], xa.x, wp.x); FMA2(acc23[0], xa.x, wp.y);
            FMA2(acc01[1], xa.y, wp.x); FMA2(acc23[1], xa.y, wp.y);
            FMA2(acc01[2], xb.x, wp.x); FMA2(acc23[2], xb.x, wp.y);
            FMA2(acc01[3], xb.y, wp.x); FMA2(acc23[3], xb.y, wp.y);
        }
        __syncthreads();
    }

    // Epilogue: coordinate transform + store channel-last.
    // oc = ty*4 + j; ty*4 even so j parity = component (0=x, 1=y).
    float b0 = bias[ty * 4 + 0];
    float b1 = bias[ty * 4 + 1];
    float b2 = bias[ty * 4 + 2];
    float b3 = bias[ty * 4 + 3];
    float ybase = (2.f * (float)y - 63.f) * (1.f / 63.f);
#pragma unroll
    for (int i = 0; i < 4; i++) {
        int pxi = tx * 4 + i;
        float xbase = (2.f * (float)pxi - 63.f) * (1.f / 63.f);
        int s = y * 64 + pxi;
        float2 f01 = *reinterpret_cast<float2*>(&acc01[i]);
        float2 f23 = *reinterpret_cast<float2*>(&acc23[i]);
        float fx0 = (xbase + tanhf(f01.x + b0) * 0.25f + 1.f) * 16.f - 0.5f;
        float fy0 = (ybase + tanhf(f01.y + b1) * 0.25f + 1.f) * 16.f - 0.5f;
        float fx1 = (xbase + tanhf(f23.x + b2) * 0.25f + 1.f) * 16.f - 0.5f;
        float fy1 = (ybase + tanhf(f23.y + b3) * 0.25f + 1.f) * 16.f - 0.5f;
        *reinterpret_cast<float4*>(
            &g_off[0] + ((size_t)b * SQ_ + s) * OC_ + ty * 4) =
            make_float4(fx0, fy0, fx1, fy1);
    }
}

// ---------------------------------------------------------------------------
// Deformable attention: one warp per (n = b*8+head, pixel). lane = channel d.
// g_off holds final sample coords in kv pixel space. Branchless taps,
// 32-bit index math (i*C_ = i<<8), K-pass keeps only (fx,fy); V-pass recomputes.
// ---------------------------------------------------------------------------
__global__ __launch_bounds__(256)
void attn_kernel() {
    int warp = threadIdx.x >> 5;
    int lane = threadIdx.x & 31;
    int n = blockIdx.y;                 // 0..63
    int s = blockIdx.x * 8 + warp;      // 0..4095
    int b = n >> 3, head = n & 7;

    int qoff = (b * SQ_ + s) * C_ + head * D_ + lane;
    float qd = g_q[qoff];
    const float* offp = &g_off[(b * SQ_ + s) * OC_ + head * (NP_ * 2)];
    const float* kb = &g_k[b * (SK_ * C_) + head * D_ + lane];
    const float* vb = &g_v[b * (SK_ * C_) + head * D_ + lane];

    float fx[NP_], fy[NP_], logit[NP_];

#pragma unroll
    for (int p = 0; p < NP_; p++) {
        float fxp = offp[2 * p + 0];
        float fyp = offp[2 * p + 1];
        fx[p] = fxp; fy[p] = fyp;
        float x0f = floorf(fxp), y0f = floorf(fyp);
        float wx1 = fxp - x0f, wy1 = fyp - y0f;
        float wx0 = 1.f - wx1, wy0 = 1.f - wy1;
        int x0i = (int)x0f, y0i = (int)y0f;
        int i00 = (y0i << 5) + x0i;
        bool vx0 = (unsigned)x0i < 32u, vx1 = (unsigned)(x0i + 1) < 32u;
        bool vy0 = (unsigned)y0i < 32u, vy1 = (unsigned)(y0i + 1) < 32u;
        float w00 = (vx0 && vy0) ? wx0 * wy0 : 0.f;
        float w01 = (vx1 && vy0) ? wx1 * wy0 : 0.f;
        float w10 = (vx0 && vy1) ? wx0 * wy1 : 0.f;
        float w11 = (vx1 && vy1) ? wx1 * wy1 : 0.f;
        int c00 = (vx0 && vy0) ? (i00 << 8)        : 0;
        int c01 = (vx1 && vy0) ? ((i00 + 1) << 8)  : 0;
        int c10 = (vx0 && vy1) ? ((i00 + 32) << 8) : 0;
        int c11 = (vx1 && vy1) ? ((i00 + 33) << 8) : 0;
        float ks = w00 * kb[c00] + w01 * kb[c01] + w10 * kb[c10] + w11 * kb[c11];
        float dot = qd * ks;
#pragma unroll
        for (int o = 16; o > 0; o >>= 1)
            dot += __shfl_xor_sync(0xffffffffu, dot, o);
        logit[p] = dot * 0.17677669529663687f;  // 1/sqrt(32)
    }

    float m = fmaxf(fmaxf(logit[0], logit[1]), fmaxf(logit[2], logit[3]));
    float e0 = __expf(logit[0] - m);
    float e1 = __expf(logit[1] - m);
    float e2 = __expf(logit[2] - m);
    float e3 = __expf(logit[3] - m);
    float inv = 1.f / (e0 + e1 + e2 + e3);
    float a[NP_] = {e0 * inv, e1 * inv, e2 * inv, e3 * inv};

    float od = 0.f;
#pragma unroll
    for (int p = 0; p < NP_; p++) {
        float x0f = floorf(fx[p]), y0f = floorf(fy[p]);
        float wx1 = fx[p] - x0f, wy1 = fy[p] - y0f;
        float wx0 = 1.f - wx1, wy0 = 1.f - wy1;
        int x0i = (int)x0f, y0i = (int)y0f;
        int i00 = (y0i << 5) + x0i;
        bool vx0 = (unsigned)x0i < 32u, vx1 = (unsigned)(x0i + 1) < 32u;
        bool vy0 = (unsigned)y0i < 32u, vy1 = (unsigned)(y0i + 1) < 32u;
        float w00 = (vx0 && vy0) ? a[p] * wx0 * wy0 : 0.f;
        float w01 = (vx1 && vy0) ? a[p] * wx1 * wy0 : 0.f;
        float w10 = (vx0 && vy1) ? a[p] * wx0 * wy1 : 0.f;
        float w11 = (vx1 && vy1) ? a[p] * wx1 * wy1 : 0.f;
        int c00 = (vx0 && vy0) ? (i00 << 8)        : 0;
        int c01 = (vx1 && vy0) ? ((i00 + 1) << 8)  : 0;
        int c10 = (vx0 && vy1) ? ((i00 + 32) << 8) : 0;
        int c11 = (vx1 && vy1) ? ((i00 + 33) << 8) : 0;
        od += w00 * vb[c00] + w01 * vb[c01] + w10 * vb[c10] + w11 * vb[c11];
    }

    g_att[qoff] = od;
}

// ---------------------------------------------------------------------------
// Launch
// ---------------------------------------------------------------------------
extern "C" void kernel_launch(void* const* d_in, const int* in_sizes, int n_in,
                              void* d_out, int out_size) {
    const float* query = (const float*)d_in[0];
    const float* kv    = (const float*)d_in[1];
    const float* q_w   = (const float*)d_in[2];
    const float* k_w   = (const float*)d_in[3];
    const float* v_w   = (const float*)d_in[4];
    const float* off_w = (const float*)d_in[5];
    const float* off_b = (const float*)d_in[6];
    const float* out_w = (const float*)d_in[7];
    float* out = (float*)d_out;

    dim3 blk16(16, 16);

    // projections (channel-last outputs)
    gemm_q_kernel <<<dim3(SQ_ / 64, C_ / 64, B_), blk16>>>(query, q_w);
    gemm_kv_kernel<<<dim3(SK_ / 64, C_ / 64, B_), blk16>>>(kv, k_w, v_w);

    // offset conv 3x3 as implicit GEMM + coord epilogue
    conv_off_gemm_kernel<<<dim3(64, B_), blk16>>>(query, off_w, off_b);

    // deformable attention
    attn_kernel<<<dim3(SQ_ / 8, B_ * NH_), 256>>>();

    // final projection to (B, C, H, W)
    gemm_out_kernel<<<dim3(SQ_ / 64, C_ / 64, B_), blk16>>>(out_w, out);
}

// round 8
// speedup vs baseline: 2.0905x; 2.0905x over previous
#include <cuda_runtime.h>
#include <math.h>

// Problem constants
#define B_   8
#define C_   256
#define SQ_  4096   // 64*64 query pixels
#define SK_  1024   // 32*32 kv pixels
#define NH_  8
#define D_   32
#define NP_  4
#define OC_  64     // offset conv out channels = NH*NP*2
#define KC_  2304   // C_*9 im2col depth

// Scratch (device globals — no allocation allowed)
__device__ float g_q  [B_ * SQ_ * C_];   // (b, s, c)  channel-last
__device__ float g_k  [B_ * SK_ * C_];   // (b, sk, c)
__device__ float g_v  [B_ * SK_ * C_];   // (b, sk, c)
__device__ float g_off[B_ * SQ_ * OC_];  // (b, s, oc) -> final sample coords (kv pixel space)
__device__ float g_att[B_ * SQ_ * C_];   // (b, s, c)

// ---------------------------------------------------------------------------
// Q projection: g_q[b][s][o] = sum_c q_w[o][c] * X[b][c][s]
// 64x64 tile, 16x16 threads, 4x4 microtile, k-major weight smem tile:
// mainloop = 2x LDS.128 + 16 FFMA per k-step.
// ---------------------------------------------------------------------------
__global__ __launch_bounds__(256)
void gemm_q_kernel(const float* __restrict__ X, const float* __restrict__ W) {
    int b  = blockIdx.z;
    int o0 = blockIdx.y * 64;
    int s0 = blockIdx.x * 64;
    int tx = threadIdx.x;          // 0..15 -> s
    int ty = threadIdx.y;          // 0..15 -> o
    int tid = ty * 16 + tx;

    __shared__ float Xs[16][64];   // [k][s]
    __shared__ float Wt[16][68];   // [k][o]  (k-major, pad 68 keeps float4 align)

    float acc[4][4];
#pragma unroll
    for (int i = 0; i < 4; i++)
#pragma unroll
        for (int j = 0; j < 4; j++) acc[i][j] = 0.f;

    for (int kc = 0; kc < C_; kc += 16) {
        {   // load X tile: 16k x 64s, float4 per thread
            int kk = tid >> 4;
            int sc = (tid & 15) * 4;
            float4 xv = *reinterpret_cast<const float4*>(
                X + ((size_t)(b * C_ + kc + kk)) * SQ_ + s0 + sc);
            *reinterpret_cast<float4*>(&Xs[kk][sc]) = xv;
        }
        {   // load W tile (o-major in gmem) and transpose into k-major smem
            int row = tid >> 2;            // o: 0..63
            int col = (tid & 3) * 4;       // k: 0,4,8,12
            float4 wv = *reinterpret_cast<const float4*>(
                W + (size_t)(o0 + row) * C_ + kc + col);
            Wt[col + 0][row] = wv.x;
            Wt[col + 1][row] = wv.y;
            Wt[col + 2][row] = wv.z;
            Wt[col + 3][row] = wv.w;
        }
        __syncthreads();
#pragma unroll
        for (int kk = 0; kk < 16; kk++) {
            float4 xv = *reinterpret_cast<const float4*>(&Xs[kk][tx * 4]);
            float4 wv = *reinterpret_cast<const float4*>(&Wt[kk][ty * 4]);
            acc[0][0] += xv.x * wv.x; acc[0][1] += xv.x * wv.y; acc[0][2] += xv.x * wv.z; acc[0][3] += xv.x * wv.w;
            acc[1][0] += xv.y * wv.x; acc[1][1] += xv.y * wv.y; acc[1][2] += xv.y * wv.z; acc[1][3] += xv.y * wv.w;
            acc[2][0] += xv.z * wv.x; acc[2][1] += xv.z * wv.y; acc[2][2] += xv.z * wv.z; acc[2][3] += xv.z * wv.w;
            acc[3][0] += xv.w * wv.x; acc[3][1] += xv.w * wv.y; acc[3][2] += xv.w * wv.z; acc[3][3] += xv.w * wv.w;
        }
        __syncthreads();
    }
#pragma unroll
    for (int i = 0; i < 4; i++) {
        float4 o4 = make_float4(acc[i][0], acc[i][1], acc[i][2], acc[i][3]);
        *reinterpret_cast<float4*>(
            g_q + ((size_t)b * SQ_ + s0 + tx * 4 + i) * C_ + o0 + ty * 4) = o4;
    }
}

// ---------------------------------------------------------------------------
// Fused K+V projection: one X tile in smem, two k-major weight tiles.
// ---------------------------------------------------------------------------
__global__ __launch_bounds__(256)
void gemm_kv_kernel(const float* __restrict__ X,
                    const float* __restrict__ Wk_g,
                    const float* __restrict__ Wv_g) {
    int b  = blockIdx.z;
    int o0 = blockIdx.y * 64;
    int s0 = blockIdx.x * 64;
    int tx = threadIdx.x;
    int ty = threadIdx.y;
    int tid = ty * 16 + tx;

    __shared__ float Xs[16][64];
    __shared__ float Wkt[16][68];
    __shared__ float Wvt[16][68];

    float acck[4][4], accv[4][4];
#pragma unroll
    for (int i = 0; i < 4; i++)
#pragma unroll
        for (int j = 0; j < 4; j++) { acck[i][j] = 0.f; accv[i][j] = 0.f; }

    for (int kc = 0; kc < C_; kc += 16) {
        {
            int kk = tid >> 4;
            int sc = (tid & 15) * 4;
            float4 xv = *reinterpret_cast<const float4*>(
                X + ((size_t)(b * C_ + kc + kk)) * SK_ + s0 + sc);
            *reinterpret_cast<float4*>(&Xs[kk][sc]) = xv;
        }
        {
            int row = tid >> 2;
            int col = (tid & 3) * 4;
            size_t woff = (size_t)(o0 + row) * C_ + kc + col;
            float4 wk = *reinterpret_cast<const float4*>(Wk_g + woff);
            float4 wv = *reinterpret_cast<const float4*>(Wv_g + woff);
            Wkt[col + 0][row] = wk.x; Wkt[col + 1][row] = wk.y;
            Wkt[col + 2][row] = wk.z; Wkt[col + 3][row] = wk.w;
            Wvt[col + 0][row] = wv.x; Wvt[col + 1][row] = wv.y;
            Wvt[col + 2][row] = wv.z; Wvt[col + 3][row] = wv.w;
        }
        __syncthreads();
#pragma unroll
        for (int kk = 0; kk < 16; kk++) {
            float4 xv = *reinterpret_cast<const float4*>(&Xs[kk][tx * 4]);
            float4 kv4 = *reinterpret_cast<const float4*>(&Wkt[kk][ty * 4]);
            acck[0][0] += xv.x * kv4.x; acck[0][1] += xv.x * kv4.y; acck[0][2] += xv.x * kv4.z; acck[0][3] += xv.x * kv4.w;
            acck[1][0] += xv.y * kv4.x; acck[1][1] += xv.y * kv4.y; acck[1][2] += xv.y * kv4.z; acck[1][3] += xv.y * kv4.w;
            acck[2][0] += xv.z * kv4.x; acck[2][1] += xv.z * kv4.y; acck[2][2] += xv.z * kv4.z; acck[2][3] += xv.z * kv4.w;
            acck[3][0] += xv.w * kv4.x; acck[3][1] += xv.w * kv4.y; acck[3][2] += xv.w * kv4.z; acck[3][3] += xv.w * kv4.w;
            float4 vv4 = *reinterpret_cast<const float4*>(&Wvt[kk][ty * 4]);
            accv[0][0] += xv.x * vv4.x; accv[0][1] += xv.x * vv4.y; accv[0][2] += xv.x * vv4.z; accv[0][3] += xv.x * vv4.w;
            accv[1][0] += xv.y * vv4.x; accv[1][1] += xv.y * vv4.y; accv[1][2] += xv.y * vv4.z; accv[1][3] += xv.y * vv4.w;
            accv[2][0] += xv.z * vv4.x; accv[2][1] += xv.z * vv4.y; accv[2][2] += xv.z * vv4.z; accv[2][3] += xv.z * vv4.w;
            accv[3][0] += xv.w * vv4.x; accv[3][1] += xv.w * vv4.y; accv[3][2] += xv.w * vv4.z; accv[3][3] += xv.w * vv4.w;
        }
        __syncthreads();
    }
#pragma unroll
    for (int i = 0; i < 4; i++) {
        size_t base = ((size_t)b * SK_ + s0 + tx * 4 + i) * C_ + o0 + ty * 4;
        *reinterpret_cast<float4*>(g_k + base) =
            make_float4(acck[i][0], acck[i][1], acck[i][2], acck[i][3]);
        *reinterpret_cast<float4*>(g_v + base) =
            make_float4(accv[i][0], accv[i][1], accv[i][2], accv[i][3]);
    }
}

// ---------------------------------------------------------------------------
// GEMM B (final projection): out[b][o][s] = sum_c W[o][c] * g_att[b][s][c]
// ---------------------------------------------------------------------------
__global__ __launch_bounds__(256)
void gemm_out_kernel(const float* __restrict__ W, float* __restrict__ Y) {
    int b  = blockIdx.z;
    int o0 = blockIdx.y * 64;
    int s0 = blockIdx.x * 64;
    int tx = threadIdx.x;          // s
    int ty = threadIdx.y;          // o
    int tid = ty * 16 + tx;

    __shared__ float As[16][68];   // [k][s]
    __shared__ float Wt[16][68];   // [k][o]

    float acc[4][4];
#pragma unroll
    for (int i = 0; i < 4; i++)
#pragma unroll
        for (int j = 0; j < 4; j++) acc[i][j] = 0.f;

    for (int kc = 0; kc < C_; kc += 16) {
        int row = tid >> 2;
        int col = (tid & 3) * 4;
        {
            float4 av = *reinterpret_cast<const float4*>(
                g_att + ((size_t)b * SQ_ + s0 + row) * C_ + kc + col);
            As[col + 0][row] = av.x; As[col + 1][row] = av.y;
            As[col + 2][row] = av.z; As[col + 3][row] = av.w;
        }
        {
            float4 wv = *reinterpret_cast<const float4*>(
                W + (size_t)(o0 + row) * C_ + kc + col);
            Wt[col + 0][row] = wv.x; Wt[col + 1][row] = wv.y;
            Wt[col + 2][row] = wv.z; Wt[col + 3][row] = wv.w;
        }
        __syncthreads();
#pragma unroll
        for (int kk = 0; kk < 16; kk++) {
            float4 xv = *reinterpret_cast<const float4*>(&As[kk][tx * 4]);
            float4 wv = *reinterpret_cast<const float4*>(&Wt[kk][ty * 4]);
            acc[0][0] += xv.x * wv.x; acc[0][1] += xv.x * wv.y; acc[0][2] += xv.x * wv.z; acc[0][3] += xv.x * wv.w;
            acc[1][0] += xv.y * wv.x; acc[1][1] += xv.y * wv.y; acc[1][2] += xv.y * wv.z; acc[1][3] += xv.y * wv.w;
            acc[2][0] += xv.z * wv.x; acc[2][1] += xv.z * wv.y; acc[2][2] += xv.z * wv.z; acc[2][3] += xv.z * wv.w;
            acc[3][0] += xv.w * wv.x; acc[3][1] += xv.w * wv.y; acc[3][2] += xv.w * wv.z; acc[3][3] += xv.w * wv.w;
        }
        __syncthreads();
    }
#pragma unroll
    for (int j = 0; j < 4; j++) {
        float4 o4 = make_float4(acc[0][j], acc[1][j], acc[2][j], acc[3][j]);
        *reinterpret_cast<float4*>(
            Y + ((size_t)b * C_ + o0 + ty * 4 + j) * SQ_ + s0 + tx * 4) = o4;
    }
}

// ---------------------------------------------------------------------------
// 3x3 SAME conv as implicit GEMM + fused coordinate epilogue.
// off(64oc, s) = W(64, 2304) x im2col(2304, s); then the epilogue converts
// each offset logit directly into the final kv-pixel-space sample coordinate:
//   f = ((base + tanh(val)*0.25) + 1) * 16 - 0.5
// ---------------------------------------------------------------------------
__global__ __launch_bounds__(256)
void conv_off_gemm_kernel(const float* __restrict__ X, const float* __restrict__ W,
                          const float* __restrict__ bias) {
    int b  = blockIdx.y;
    int y  = blockIdx.x;           // image row = s-tile of 64 pixels
    int tx = threadIdx.x;          // 0..15 -> s (x position groups)
    int ty = threadIdx.y;          // 0..15 -> oc
    int tid = ty * 16 + tx;

    __shared__ float Xs[16][64];   // [k][x]
    __shared__ float Wt[16][68];   // [k][oc]

    float acc[4][4];
#pragma unroll
    for (int i = 0; i < 4; i++)
#pragma unroll
        for (int j = 0; j < 4; j++) acc[i][j] = 0.f;

    for (int kc = 0; kc < KC_; kc += 16) {
        {   // gather im2col tile: 16 K-rows x 64 x-positions
            int kk   = tid >> 4;            // 0..15
            int xc   = (tid & 15) * 4;      // 0,4,...,60
            int kidx = kc + kk;
            int c    = kidx / 9;
            int r9   = kidx - c * 9;
            int ky   = r9 / 3 - 1;          // -1,0,1
            int kx   = r9 - (r9 / 3) * 3 - 1;
            int gy   = y + ky;
            float v0 = 0.f, v1 = 0.f, v2 = 0.f, v3 = 0.f;
            if (gy >= 0 && gy < 64) {
                const float* rowp = X + (((size_t)b * C_ + c) * 64 + gy) * 64;
                int g0 = xc + 0 + kx, g1 = xc + 1 + kx, g2 = xc + 2 + kx, g3 = xc + 3 + kx;
                if (g0 >= 0 && g0 < 64) v0 = rowp[g0];
                if (g1 >= 0 && g1 < 64) v1 = rowp[g1];
                if (g2 >= 0 && g2 < 64) v2 = rowp[g2];
                if (g3 >= 0 && g3 < 64) v3 = rowp[g3];
            }
            Xs[kk][xc + 0] = v0; Xs[kk][xc + 1] = v1;
            Xs[kk][xc + 2] = v2; Xs[kk][xc + 3] = v3;
        }
        {   // load W tile (oc-major in gmem, contiguous k) -> k-major smem
            int row = tid >> 2;            // oc
            int col = (tid & 3) * 4;       // k
            float4 wv = *reinterpret_cast<const float4*>(
                W + (size_t)row * KC_ + kc + col);
            Wt[col + 0][row] = wv.x;
            Wt[col + 1][row] = wv.y;
            Wt[col + 2][row] = wv.z;
            Wt[col + 3][row] = wv.w;
        }
        __syncthreads();
#pragma unroll
        for (int kk = 0; kk < 16; kk++) {
            float4 xv = *reinterpret_cast<const float4*>(&Xs[kk][tx * 4]);
            float4 wv = *reinterpret_cast<const float4*>(&Wt[kk][ty * 4]);
            acc[0][0] += xv.x * wv.x; acc[0][1] += xv.x * wv.y; acc[0][2] += xv.x * wv.z; acc[0][3] += xv.x * wv.w;
            acc[1][0] += xv.y * wv.x; acc[1][1] += xv.y * wv.y; acc[1][2] += xv.y * wv.z; acc[1][3] += xv.y * wv.w;
            acc[2][0] += xv.z * wv.x; acc[2][1] += xv.z * wv.y; acc[2][2] += xv.z * wv.z; acc[2][3] += xv.z * wv.w;
            acc[3][0] += xv.w * wv.x; acc[3][1] += xv.w * wv.y; acc[3][2] += xv.w * wv.z; acc[3][3] += xv.w * wv.w;
        }
        __syncthreads();
    }

    // Epilogue: coordinate transform + store channel-last.
    // oc = ty*4 + j; ty*4 is even so (j & 1) == component (0=x, 1=y).
    float b0 = bias[ty * 4 + 0];
    float b1 = bias[ty * 4 + 1];
    float b2 = bias[ty * 4 + 2];
    float b3 = bias[ty * 4 + 3];
    float ybase = (2.f * (float)y - 63.f) * (1.f / 63.f);   // normalized y of this row
#pragma unroll
    for (int i = 0; i < 4; i++) {
        int pxi = tx * 4 + i;
        float xbase = (2.f * (float)pxi - 63.f) * (1.f / 63.f);
        int s = y * 64 + pxi;
        // comp pattern over j = 0,1,2,3 is x,y,x,y
        float fx0 = (xbase + tanhf(acc[i][0] + b0) * 0.25f + 1.f) * 16.f - 0.5f;
        float fy0 = (ybase + tanhf(acc[i][1] + b1) * 0.25f + 1.f) * 16.f - 0.5f;
        float fx1 = (xbase + tanhf(acc[i][2] + b2) * 0.25f + 1.f) * 16.f - 0.5f;
        float fy1 = (ybase + tanhf(acc[i][3] + b3) * 0.25f + 1.f) * 16.f - 0.5f;
        float4 o4 = make_float4(fx0, fy0, fx1, fy1);
        *reinterpret_cast<float4*>(
            &g_off[0] + ((size_t)b * SQ_ + s) * OC_ + ty * 4) = o4;
    }
}

// ---------------------------------------------------------------------------
// Deformable attention: one warp per (n = b*8+head, pixel). lane = channel d.
// g_off holds final sample coords in kv pixel space; no tanh/grid math here.
// ---------------------------------------------------------------------------
__global__ __launch_bounds__(256)
void attn_kernel() {
    int warp = threadIdx.x >> 5;
    int lane = threadIdx.x & 31;
    int n = blockIdx.y;                 // 0..63
    int s = blockIdx.x * 8 + warp;      // 0..4095
    int b = n >> 3, head = n & 7;

    float qd = g_q[((size_t)b * SQ_ + s) * C_ + head * D_ + lane];
    const float* offp = &g_off[((size_t)b * SQ_ + s) * OC_ + head * (NP_ * 2)];
    const float* kb = &g_k[(size_t)b * SK_ * C_ + head * D_ + lane];
    const float* vb = &g_v[(size_t)b * SK_ * C_ + head * D_ + lane];

    float logit[NP_];
    int   tidx[NP_][4];
    float twgt[NP_][4];

#pragma unroll
    for (int p = 0; p < NP_; p++) {
        float fx = offp[2 * p + 0];
        float fy = offp[2 * p + 1];
        float x0 = floorf(fx), y0 = floorf(fy);
        float wx1 = fx - x0, wy1 = fy - y0;
        int x0i = (int)x0, y0i = (int)y0;

        float ks = 0.f;
#pragma unroll
        for (int t = 0; t < 4; t++) {
            int dy = t >> 1, dx = t & 1;
            int xi = x0i + dx, yi = y0i + dy;
            bool valid = (xi >= 0) && (xi < 32) && (yi >= 0) && (yi < 32);
            float wgt = (dx ? wx1 : 1.f - wx1) * (dy ? wy1 : 1.f - wy1);
            tidx[p][t] = valid ? (yi * 32 + xi) : -1;
            twgt[p][t] = valid ? wgt : 0.f;
            if (valid) ks += wgt * kb[(size_t)(yi * 32 + xi) * C_];
        }
        float dot = qd * ks;
#pragma unroll
        for (int o = 16; o > 0; o >>= 1)
            dot += __shfl_xor_sync(0xffffffffu, dot, o);
        logit[p] = dot * 0.17677669529663687f;  // 1/sqrt(32)
    }

    float m = fmaxf(fmaxf(logit[0], logit[1]), fmaxf(logit[2], logit[3]));
    float e0 = __expf(logit[0] - m);
    float e1 = __expf(logit[1] - m);
    float e2 = __expf(logit[2] - m);
    float e3 = __expf(logit[3] - m);
    float inv = 1.f / (e0 + e1 + e2 + e3);
    float a[NP_] = {e0 * inv, e1 * inv, e2 * inv, e3 * inv};

    float od = 0.f;
#pragma unroll
    for (int p = 0; p < NP_; p++)
#pragma unroll
        for (int t = 0; t < 4; t++)
            if (tidx[p][t] >= 0)
                od += a[p] * twgt[p][t] * vb[(size_t)tidx[p][t] * C_];

    g_att[((size_t)b * SQ_ + s) * C_ + head * D_ + lane] = od;
}

// ---------------------------------------------------------------------------
// Launch
// ---------------------------------------------------------------------------
extern "C" void kernel_launch(void* const* d_in, const int* in_sizes, int n_in,
                              void* d_out, int out_size) {
    const float* query = (const float*)d_in[0];
    const float* kv    = (const float*)d_in[1];
    const float* q_w   = (const float*)d_in[2];
    const float* k_w   = (const float*)d_in[3];
    const float* v_w   = (const float*)d_in[4];
    const float* off_w = (const float*)d_in[5];
    const float* off_b = (const float*)d_in[6];
    const float* out_w = (const float*)d_in[7];
    float* out = (float*)d_out;

    dim3 blk16(16, 16);

    // projections (channel-last outputs)
    gemm_q_kernel <<<dim3(SQ_ / 64, C_ / 64, B_), blk16>>>(query, q_w);
    gemm_kv_kernel<<<dim3(SK_ / 64, C_ / 64, B_), blk16>>>(kv, k_w, v_w);

    // offset conv 3x3 as implicit GEMM + coord epilogue
    conv_off_gemm_kernel<<<dim3(64, B_), blk16>>>(query, off_w, off_b);

    // deformable attention
    attn_kernel<<<dim3(SQ_ / 8, B_ * NH_), 256>>>();

    // final projection to (B, C, H, W)
    gemm_out_kernel<<<dim3(SQ_ / 64, C_ / 64, B_), blk16>>>(out_w, out);
}